// round 1
// baseline (speedup 1.0000x reference)
#include <cuda_runtime.h>
#include <float.h>

#define NROWS 8192
#define DIM   2048

// Scratch (device globals — no allocation allowed)
__device__ float g_K[(size_t)NROWS * DIM];
__device__ float g_Q[(size_t)NROWS * DIM];
__device__ float g_V[(size_t)NROWS * DIM];
__device__ float g_ATT[(size_t)DIM * DIM];
__device__ float g_O[(size_t)NROWS * DIM];

constexpr int BM = 128, BN = 128, BK = 16;

// ---------------------------------------------------------------------------
// Tile load/store helpers
// AMODE 0: A is M x K row-major (lda = K). Tile A[m0..m0+127][k0..k0+15]
// AMODE 1: As[kk][mm] = A[(k0+kk)*lda + m0+mm]   (used for Q^T K: wide load)
// BMODE 0: Bs[kk][nn] = B[(k0+kk)*ldb + n0+nn]   (B is K x N row-major)
// BMODE 1: Bs[kk][nn] = B[(n0+nn)*ldb + k0+kk]   (B is N x K row-major, i.e. B^T)
// ---------------------------------------------------------------------------
template <int AMODE>
__device__ __forceinline__ void load_a(const float* __restrict__ A, int lda,
                                       int m0, int k0, int tid, float4 (&va)[2]) {
#pragma unroll
    for (int u = 0; u < 2; u++) {
        int f = tid + u * 256;
        if (AMODE == 0) {
            int row = f >> 2, k4 = f & 3;
            va[u] = *(const float4*)&A[(size_t)(m0 + row) * lda + k0 + k4 * 4];
        } else {
            int kk = f >> 5, m4 = f & 31;
            va[u] = *(const float4*)&A[(size_t)(k0 + kk) * lda + m0 + m4 * 4];
        }
    }
}

template <int AMODE>
__device__ __forceinline__ void store_a(float (&As)[BK][BM], int tid, const float4 (&va)[2]) {
#pragma unroll
    for (int u = 0; u < 2; u++) {
        int f = tid + u * 256;
        if (AMODE == 0) {
            int row = f >> 2, k4 = f & 3;
            As[k4 * 4 + 0][row] = va[u].x;
            As[k4 * 4 + 1][row] = va[u].y;
            As[k4 * 4 + 2][row] = va[u].z;
            As[k4 * 4 + 3][row] = va[u].w;
        } else {
            int kk = f >> 5, m4 = f & 31;
            *(float4*)&As[kk][m4 * 4] = va[u];
        }
    }
}

template <int BMODE>
__device__ __forceinline__ void load_b(const float* __restrict__ B, int ldb,
                                       int n0, int k0, int tid, float4 (&vb)[2]) {
#pragma unroll
    for (int u = 0; u < 2; u++) {
        int f = tid + u * 256;
        if (BMODE == 0) {
            int kk = f >> 5, n4 = f & 31;
            vb[u] = *(const float4*)&B[(size_t)(k0 + kk) * ldb + n0 + n4 * 4];
        } else {
            int nn = f >> 2, k4 = f & 3;
            vb[u] = *(const float4*)&B[(size_t)(n0 + nn) * ldb + k0 + k4 * 4];
        }
    }
}

template <int BMODE>
__device__ __forceinline__ void store_b(float (&Bs)[BK][BN], int tid, const float4 (&vb)[2]) {
#pragma unroll
    for (int u = 0; u < 2; u++) {
        int f = tid + u * 256;
        if (BMODE == 0) {
            int kk = f >> 5, n4 = f & 31;
            *(float4*)&Bs[kk][n4 * 4] = vb[u];
        } else {
            int nn = f >> 2, k4 = f & 3;
            Bs[k4 * 4 + 0][nn] = vb[u].x;
            Bs[k4 * 4 + 1][nn] = vb[u].y;
            Bs[k4 * 4 + 2][nn] = vb[u].z;
            Bs[k4 * 4 + 3][nn] = vb[u].w;
        }
    }
}

// ---------------------------------------------------------------------------
// Tiled SGEMM: C[M,N] = opA(A) * opB(B) (+ bias[N]) (+ res[M,N])
// 256 threads, 8x8 per thread in 2x2 quadrants of 4x4, double-buffered smem.
// All dims assumed multiples of BM/BN/BK (they are: 8192/2048).
// ---------------------------------------------------------------------------
template <int AMODE, int BMODE, bool HAS_BIAS, bool HAS_RES>
__global__ void __launch_bounds__(256) gemm_kernel(
    const float* __restrict__ A, const float* __restrict__ B,
    const float* __restrict__ bias, const float* __restrict__ res,
    float* __restrict__ C, int M, int N, int K, int lda, int ldb, int ldc) {
    __shared__ __align__(16) float As[2][BK][BM];
    __shared__ __align__(16) float Bs[2][BK][BN];

    const int tid = threadIdx.x;
    const int m0 = blockIdx.y * BM;
    const int n0 = blockIdx.x * BN;
    const int tx = tid & 15;
    const int ty = tid >> 4;

    float acc[8][8];
#pragma unroll
    for (int i = 0; i < 8; i++)
#pragma unroll
        for (int j = 0; j < 8; j++) acc[i][j] = 0.f;

    float4 va[2], vb[2];
    load_a<AMODE>(A, lda, m0, 0, tid, va);
    load_b<BMODE>(B, ldb, n0, 0, tid, vb);
    store_a<AMODE>(As[0], tid, va);
    store_b<BMODE>(Bs[0], tid, vb);
    __syncthreads();

    const int ntiles = K / BK;
    int cur = 0;
    for (int t = 0; t < ntiles; t++) {
        if (t + 1 < ntiles) {
            load_a<AMODE>(A, lda, m0, (t + 1) * BK, tid, va);
            load_b<BMODE>(B, ldb, n0, (t + 1) * BK, tid, vb);
        }
#pragma unroll
        for (int kk = 0; kk < BK; kk++) {
            float a[8], b[8];
            *(float4*)&a[0] = *(float4*)&As[cur][kk][ty * 4];
            *(float4*)&a[4] = *(float4*)&As[cur][kk][64 + ty * 4];
            *(float4*)&b[0] = *(float4*)&Bs[cur][kk][tx * 4];
            *(float4*)&b[4] = *(float4*)&Bs[cur][kk][64 + tx * 4];
#pragma unroll
            for (int i = 0; i < 8; i++)
#pragma unroll
                for (int j = 0; j < 8; j++) acc[i][j] += a[i] * b[j];
        }
        if (t + 1 < ntiles) {
            store_a<AMODE>(As[cur ^ 1], tid, va);
            store_b<BMODE>(Bs[cur ^ 1], tid, vb);
            __syncthreads();
            cur ^= 1;
        }
    }

    // Epilogue
#pragma unroll
    for (int ih = 0; ih < 2; ih++) {
#pragma unroll
        for (int i = 0; i < 4; i++) {
            int row = m0 + ih * 64 + ty * 4 + i;
#pragma unroll
            for (int jh = 0; jh < 2; jh++) {
                int col = n0 + jh * 64 + tx * 4;
                float4 v;
                v.x = acc[ih * 4 + i][jh * 4 + 0];
                v.y = acc[ih * 4 + i][jh * 4 + 1];
                v.z = acc[ih * 4 + i][jh * 4 + 2];
                v.w = acc[ih * 4 + i][jh * 4 + 3];
                if (HAS_BIAS) {
                    float4 bv = *(const float4*)&bias[col];
                    v.x += bv.x; v.y += bv.y; v.z += bv.z; v.w += bv.w;
                }
                if (HAS_RES) {
                    float4 rv = *(const float4*)&res[(size_t)row * ldc + col];
                    v.x += rv.x; v.y += rv.y; v.z += rv.z; v.w += rv.w;
                }
                *(float4*)&C[(size_t)row * ldc + col] = v;
            }
        }
    }
}

// ---------------------------------------------------------------------------
// Row softmax: one 256-thread block per row of length DIM (2048)
// ---------------------------------------------------------------------------
__global__ void __launch_bounds__(256) softmax_kernel(const float* __restrict__ in,
                                                      float* __restrict__ out, int n) {
    const int row = blockIdx.x;
    const int tid = threadIdx.x;
    const float* r = in + (size_t)row * n;
    __shared__ float red[8];

    float v[8];
    float mx = -FLT_MAX;
#pragma unroll
    for (int i = 0; i < 8; i++) {
        v[i] = r[tid + i * 256];
        mx = fmaxf(mx, v[i]);
    }
#pragma unroll
    for (int o = 16; o > 0; o >>= 1) mx = fmaxf(mx, __shfl_xor_sync(0xffffffffu, mx, o));
    if ((tid & 31) == 0) red[tid >> 5] = mx;
    __syncthreads();
    mx = red[0];
#pragma unroll
    for (int w = 1; w < 8; w++) mx = fmaxf(mx, red[w]);
    __syncthreads();

    float s = 0.f;
#pragma unroll
    for (int i = 0; i < 8; i++) {
        v[i] = __expf(v[i] - mx);
        s += v[i];
    }
#pragma unroll
    for (int o = 16; o > 0; o >>= 1) s += __shfl_xor_sync(0xffffffffu, s, o);
    if ((tid & 31) == 0) red[tid >> 5] = s;
    __syncthreads();
    s = red[0];
#pragma unroll
    for (int w = 1; w < 8; w++) s += red[w];
    float inv = 1.f / s;

    float* o = out + (size_t)row * n;
#pragma unroll
    for (int i = 0; i < 8; i++) o[tid + i * 256] = v[i] * inv;
}

// ---------------------------------------------------------------------------
// Host-side branch driver
// ---------------------------------------------------------------------------
static void run_branch(const float* X, const float* Kw, const float* Kb,
                       const float* Qw, const float* Qb, const float* Vw, const float* Vb,
                       const float* Ow, const float* Ob, float* outY, float* outW,
                       float* gK, float* gQ, float* gV, float* gATT, float* gO) {
    dim3 blk(256);
    dim3 gProj(DIM / BN, NROWS / BM);  // (16, 64)
    dim3 gAtt(DIM / BN, DIM / BM);     // (16, 16)

    // K/Q/V projections: C = X @ W + b
    gemm_kernel<0, 0, true, false><<<gProj, blk>>>(X, Kw, Kb, nullptr, gK, NROWS, DIM, DIM, DIM, DIM, DIM);
    gemm_kernel<0, 0, true, false><<<gProj, blk>>>(X, Qw, Qb, nullptr, gQ, NROWS, DIM, DIM, DIM, DIM, DIM);
    gemm_kernel<0, 0, true, false><<<gProj, blk>>>(X, Vw, Vb, nullptr, gV, NROWS, DIM, DIM, DIM, DIM, DIM);
    // att = Q^T @ K   [DIM, DIM], contraction over NROWS
    gemm_kernel<1, 0, false, false><<<gAtt, blk>>>(gQ, gK, nullptr, nullptr, gATT, DIM, DIM, NROWS, DIM, DIM, DIM);
    // w = softmax(att) -> directly into output region (also consumed below)
    softmax_kernel<<<DIM, blk>>>(gATT, outW, DIM);
    // out = V @ w^T
    gemm_kernel<0, 1, false, false><<<gProj, blk>>>(gV, outW, nullptr, nullptr, gO, NROWS, DIM, DIM, DIM, DIM, DIM);
    // y = out @ Ow + Ob + X
    gemm_kernel<0, 0, true, true><<<gProj, blk>>>(gO, Ow, Ob, X, outY, NROWS, DIM, DIM, DIM, DIM, DIM);
}

extern "C" void kernel_launch(void* const* d_in, const int* in_sizes, int n_in,
                              void* d_out, int out_size) {
    const float* x   = (const float*)d_in[0];
    const float* y   = (const float*)d_in[1];
    const float* QKw = (const float*)d_in[2];
    const float* QKb = (const float*)d_in[3];
    const float* QQw = (const float*)d_in[4];
    const float* QQb = (const float*)d_in[5];
    const float* QVw = (const float*)d_in[6];
    const float* QVb = (const float*)d_in[7];
    const float* QOw = (const float*)d_in[8];
    const float* QOb = (const float*)d_in[9];
    const float* FKw = (const float*)d_in[10];
    const float* FKb = (const float*)d_in[11];
    const float* FQw = (const float*)d_in[12];
    const float* FQb = (const float*)d_in[13];
    const float* FVw = (const float*)d_in[14];
    const float* FVb = (const float*)d_in[15];
    const float* FOw = (const float*)d_in[16];
    const float* FOb = (const float*)d_in[17];

    float* out = (float*)d_out;
    float* outQy   = out;                                   // [8192, 2048]
    float* outQatt = outQy + (size_t)NROWS * DIM;           // [2048, 2048]
    float* outFy   = outQatt + (size_t)DIM * DIM;           // [8192, 2048]
    float* outFatt = outFy + (size_t)NROWS * DIM;           // [2048, 2048]

    float *gK, *gQ, *gV, *gATT, *gO;
    cudaGetSymbolAddress((void**)&gK, g_K);
    cudaGetSymbolAddress((void**)&gQ, g_Q);
    cudaGetSymbolAddress((void**)&gV, g_V);
    cudaGetSymbolAddress((void**)&gATT, g_ATT);
    cudaGetSymbolAddress((void**)&gO, g_O);

    run_branch(x, QKw, QKb, QQw, QQb, QVw, QVb, QOw, QOb, outQy, outQatt, gK, gQ, gV, gATT, gO);
    run_branch(y, FKw, FKb, FQw, FQb, FVw, FVb, FOw, FOb, outFy, outFatt, gK, gQ, gV, gATT, gO);
}

// round 4
// speedup vs baseline: 3.6211x; 3.6211x over previous
#include <cuda_runtime.h>
#include <cuda_fp16.h>
#include <float.h>

#define NROWS 8192
#define DIM   2048

typedef unsigned short u16;
typedef unsigned int   u32;
typedef unsigned long long u64;

// ---------------- scratch (device globals; no allocation allowed) ----------------
__device__ u16 g_Xh[(size_t)NROWS*DIM], g_Xl[(size_t)NROWS*DIM];
__device__ u16 g_Wth[(size_t)DIM*DIM],  g_Wtl[(size_t)DIM*DIM];
__device__ float g_Kf[(size_t)NROWS*DIM], g_Qf[(size_t)NROWS*DIM];
__device__ u16 g_Kth[(size_t)NROWS*DIM], g_Ktl[(size_t)NROWS*DIM];
__device__ u16 g_Qth[(size_t)NROWS*DIM], g_Qtl[(size_t)NROWS*DIM];
__device__ u16 g_Vh[(size_t)NROWS*DIM],  g_Vl[(size_t)NROWS*DIM];
__device__ float g_ATT[(size_t)DIM*DIM];
__device__ u16 g_wh[(size_t)DIM*DIM],   g_wl[(size_t)DIM*DIM];
__device__ u16 g_Oh[(size_t)NROWS*DIM], g_Ol[(size_t)NROWS*DIM];

// ---------------- helpers ----------------
__device__ __forceinline__ u32 smem_u32(const void* p) {
    u32 a;
    asm("{ .reg .u64 t; cvta.to.shared.u64 t, %1; cvt.u32.u64 %0, t; }" : "=r"(a) : "l"(p));
    return a;
}

__device__ __forceinline__ void split1h(float v, u16& h, u16& l) {
    __half hh = __float2half_rn(v);
    float r = v - __half2float(hh);
    __half ll = __float2half_rn(r);
    h = __half_as_ushort(hh);
    l = __half_as_ushort(ll);
}

#define CP_ASYNC16(dst, src) \
    asm volatile("cp.async.cg.shared.global [%0], [%1], 16;" :: "r"(dst), "l"(src))
#define CP_COMMIT()  asm volatile("cp.async.commit_group;" ::: "memory")
#define CP_WAIT0()   asm volatile("cp.async.wait_group 0;" ::: "memory")
#define CP_WAIT1()   asm volatile("cp.async.wait_group 1;" ::: "memory")

#define LDSM_X4(r, addr) \
    asm volatile("ldmatrix.sync.aligned.m8n8.x4.shared.b16 {%0,%1,%2,%3}, [%4];" \
        : "=r"((r)[0]), "=r"((r)[1]), "=r"((r)[2]), "=r"((r)[3]) : "r"(addr))

#define MMA16816(d, a, b) \
    asm volatile("mma.sync.aligned.m16n8k16.row.col.f32.f16.f16.f32 " \
        "{%0,%1,%2,%3}, {%4,%5,%6,%7}, {%8,%9}, {%0,%1,%2,%3};" \
        : "+f"((d)[0]), "+f"((d)[1]), "+f"((d)[2]), "+f"((d)[3]) \
        : "r"((a)[0]), "r"((a)[1]), "r"((a)[2]), "r"((a)[3]), "r"((b)[0]), "r"((b)[1]))

// ---------------- GEMM: C[M,N] = A * B^T via fp16x3 split, fp32 accum ----------------
// A planes: [M][K] fp16 hi/lo row-major; B planes: [N][K] fp16 hi/lo row-major.
// CTA tile 128x128, BK=64 elems (128B rows, full 8-chunk xor swizzle).
constexpr int PLANE_BYTES = 128 * 128;          // 16KB: 128 rows x 64 fp16
constexpr int STAGE_BYTES = 4 * PLANE_BYTES;    // Ah, Al, Bh, Bl
constexpr int NSTAGE = 3;
constexpr int SMEM_TOTAL = NSTAGE * STAGE_BYTES;  // 196608

template <bool EMIT, bool BIAS, bool RES>
__global__ void __launch_bounds__(256, 1) gemm_fp16x3(
    const u16* __restrict__ Ah_, const u16* __restrict__ Al_,
    const u16* __restrict__ Bh_, const u16* __restrict__ Bl_,
    const float* __restrict__ bias, const float* __restrict__ res,
    float* __restrict__ C, u16* __restrict__ Ch, u16* __restrict__ Cl,
    int M, int N, int K) {
    extern __shared__ char smem[];
    const int tid = threadIdx.x;
    const int lane = tid & 31;
    const int wid = tid >> 5;
    const int warpM = wid & 1;   // 2 tiles of 64 rows
    const int warpN = wid >> 1;  // 4 tiles of 32 cols
    const int m0 = blockIdx.y * 128;
    const int n0 = blockIdx.x * 128;
    const u32 sb = smem_u32(smem);

    float acc[4][4][4];
#pragma unroll
    for (int i = 0; i < 4; i++)
#pragma unroll
        for (int j = 0; j < 4; j++)
#pragma unroll
            for (int k = 0; k < 4; k++) acc[i][j][k] = 0.f;

    const u16* planes[4] = {Ah_, Al_, Bh_, Bl_};

    // issue cp.async for k-tile t into stage t%NSTAGE
    auto issue = [&](int t) {
        const int k0 = t * 64;
        const u32 stg = sb + (t % NSTAGE) * STAGE_BYTES;
#pragma unroll
        for (int p = 0; p < 4; p++) {
            const u16* src = planes[p];
            const int r0 = (p < 2) ? m0 : n0;
            const u32 pb = stg + p * PLANE_BYTES;
#pragma unroll
            for (int it = 0; it < 4; it++) {
                int idx = tid + it * 256;
                int r = idx >> 3, c = idx & 7;
                const u16* g = src + (size_t)(r0 + r) * K + k0 + c * 8;
                u32 d = pb + r * 128 + ((c ^ (r & 7)) << 4);
                CP_ASYNC16(d, g);
            }
        }
    };

    issue(0); CP_COMMIT();
    issue(1); CP_COMMIT();

    const int T = K / 64;
    for (int t = 0; t < T; t++) {
        if (t + 2 < T) { CP_WAIT1(); } else { CP_WAIT0(); }
        __syncthreads();

        const u32 stg = sb + (t % NSTAGE) * STAGE_BYTES;
        const u32 aH = stg, aL = stg + PLANE_BYTES;
        const u32 bH = stg + 2 * PLANE_BYTES, bL = stg + 3 * PLANE_BYTES;

#pragma unroll
        for (int step = 0; step < 4; step++) {
            u32 ra[4][4], la[4][4];
#pragma unroll
            for (int mf = 0; mf < 4; mf++) {
                int row = warpM * 64 + mf * 16 + (lane & 15);
                int chunk = step * 2 + (lane >> 4);
                u32 off = row * 128 + ((chunk ^ (row & 7)) << 4);
                LDSM_X4(ra[mf], aH + off);
                LDSM_X4(la[mf], aL + off);
            }
            u32 rb[2][4], lb[2][4];
#pragma unroll
            for (int np = 0; np < 2; np++) {
                int j = lane >> 3;
                int row = warpN * 32 + np * 16 + ((j >> 1) << 3) + (lane & 7);
                int chunk = step * 2 + (j & 1);
                u32 off = row * 128 + ((chunk ^ (row & 7)) << 4);
                LDSM_X4(rb[np], bH + off);
                LDSM_X4(lb[np], bL + off);
            }
            // 3 split products; 16 independent accumulator chains per pass
#pragma unroll
            for (int mf = 0; mf < 4; mf++)
#pragma unroll
                for (int nf = 0; nf < 4; nf++)
                    MMA16816(acc[mf][nf], ra[mf], &rb[nf >> 1][(nf & 1) * 2]);
#pragma unroll
            for (int mf = 0; mf < 4; mf++)
#pragma unroll
                for (int nf = 0; nf < 4; nf++)
                    MMA16816(acc[mf][nf], ra[mf], &lb[nf >> 1][(nf & 1) * 2]);
#pragma unroll
            for (int mf = 0; mf < 4; mf++)
#pragma unroll
                for (int nf = 0; nf < 4; nf++)
                    MMA16816(acc[mf][nf], la[mf], &rb[nf >> 1][(nf & 1) * 2]);
        }

        if (t + 2 < T) { issue(t + 2); CP_COMMIT(); }
    }

    // ---------------- epilogue: direct register stores ----------------
#pragma unroll
    for (int mf = 0; mf < 4; mf++) {
        const int rbase = m0 + warpM * 64 + mf * 16 + (lane >> 2);
#pragma unroll
        for (int nf = 0; nf < 4; nf++) {
            const int c = n0 + warpN * 32 + nf * 8 + (lane & 3) * 2;
            const float* a = acc[mf][nf];
#pragma unroll
            for (int h = 0; h < 2; h++) {
                const int r = rbase + h * 8;
                float vx = a[h * 2 + 0], vy = a[h * 2 + 1];
                if (BIAS) {
                    float2 b2 = *(const float2*)&bias[c];
                    vx += b2.x; vy += b2.y;
                }
                if (RES) {
                    float2 r2 = *(const float2*)&res[(size_t)r * N + c];
                    vx += r2.x; vy += r2.y;
                }
                if (EMIT) {
                    u16 hx, lx, hy, ly;
                    split1h(vx, hx, lx);
                    split1h(vy, hy, ly);
                    *(ushort2*)&Ch[(size_t)r * N + c] = make_ushort2(hx, hy);
                    *(ushort2*)&Cl[(size_t)r * N + c] = make_ushort2(lx, ly);
                } else {
                    *(float2*)&C[(size_t)r * N + c] = make_float2(vx, vy);
                }
            }
        }
    }
}

// ---------------- conversion kernels ----------------
__global__ void __launch_bounds__(256) convert_plain(const float* __restrict__ in,
                                                     u16* __restrict__ hi, u16* __restrict__ lo,
                                                     size_t n4) {
    size_t i = (size_t)blockIdx.x * 256 + threadIdx.x;
    if (i >= n4) return;
    float4 v = ((const float4*)in)[i];
    ushort4 h, l;
    split1h(v.x, h.x, l.x); split1h(v.y, h.y, l.y);
    split1h(v.z, h.z, l.z); split1h(v.w, h.w, l.w);
    ((ushort4*)hi)[i] = h;
    ((ushort4*)lo)[i] = l;
}

// in: [R][C] fp32 -> out planes [C][R] fp16 hi/lo
__global__ void __launch_bounds__(256) convert_trans(const float* __restrict__ in,
                                                     u16* __restrict__ hi, u16* __restrict__ lo,
                                                     int R, int C) {
    __shared__ float t[32][33];
    const int c0 = blockIdx.x * 32, r0 = blockIdx.y * 32;
    const int tx = threadIdx.x & 31, ty = threadIdx.x >> 5;  // 32x8
#pragma unroll
    for (int j = 0; j < 32; j += 8)
        t[ty + j][tx] = in[(size_t)(r0 + ty + j) * C + c0 + tx];
    __syncthreads();
#pragma unroll
    for (int j = 0; j < 32; j += 8) {
        float v = t[tx][ty + j];
        u16 h, l;
        split1h(v, h, l);
        size_t o = (size_t)(c0 + ty + j) * R + r0 + tx;
        hi[o] = h;
        lo[o] = l;
    }
}

// ---------------- softmax (+ emit fp16 planes of w) ----------------
__global__ void __launch_bounds__(256) softmax_kernel(const float* __restrict__ in,
                                                      float* __restrict__ out,
                                                      u16* __restrict__ wh, u16* __restrict__ wl,
                                                      int n) {
    const int row = blockIdx.x;
    const int tid = threadIdx.x;
    const float* r = in + (size_t)row * n;
    __shared__ float red[8];

    float v[8];
    float mx = -FLT_MAX;
#pragma unroll
    for (int i = 0; i < 8; i++) {
        v[i] = r[tid + i * 256];
        mx = fmaxf(mx, v[i]);
    }
#pragma unroll
    for (int o = 16; o > 0; o >>= 1) mx = fmaxf(mx, __shfl_xor_sync(0xffffffffu, mx, o));
    if ((tid & 31) == 0) red[tid >> 5] = mx;
    __syncthreads();
    mx = red[0];
#pragma unroll
    for (int w = 1; w < 8; w++) mx = fmaxf(mx, red[w]);
    __syncthreads();

    float s = 0.f;
#pragma unroll
    for (int i = 0; i < 8; i++) {
        v[i] = __expf(v[i] - mx);
        s += v[i];
    }
#pragma unroll
    for (int o = 16; o > 0; o >>= 1) s += __shfl_xor_sync(0xffffffffu, s, o);
    if ((tid & 31) == 0) red[tid >> 5] = s;
    __syncthreads();
    s = red[0];
#pragma unroll
    for (int w = 1; w < 8; w++) s += red[w];
    const float inv = 1.f / s;

    float* o = out + (size_t)row * n;
#pragma unroll
    for (int i = 0; i < 8; i++) {
        float w = v[i] * inv;
        int col = tid + i * 256;
        o[col] = w;
        u16 h, l;
        split1h(w, h, l);
        wh[(size_t)row * n + col] = h;
        wl[(size_t)row * n + col] = l;
    }
}

// ---------------- host driver ----------------
struct Scratch {
    u16 *Xh, *Xl, *Wth, *Wtl, *Kth, *Ktl, *Qth, *Qtl, *Vh, *Vl, *wh, *wl, *Oh, *Ol;
    float *Kf, *Qf, *ATT;
};

static void run_branch(const Scratch& S, const float* X,
                       const float* Kw, const float* Kb, const float* Qw, const float* Qb,
                       const float* Vw, const float* Vb, const float* Ow, const float* Ob,
                       float* outY, float* outW) {
    dim3 b256(256);
    const size_t nX4 = (size_t)NROWS * DIM / 4;
    dim3 gW(DIM / 32, DIM / 32);
    dim3 gT(DIM / 32, NROWS / 32);
    dim3 gProj(DIM / 128, NROWS / 128);  // (16, 64)
    dim3 gAtt(DIM / 128, DIM / 128);     // (16, 16)

    convert_plain<<<(unsigned)(nX4 / 256), b256>>>(X, S.Xh, S.Xl, nX4);

    convert_trans<<<gW, b256>>>(Kw, S.Wth, S.Wtl, DIM, DIM);
    gemm_fp16x3<false, true, false><<<gProj, b256, SMEM_TOTAL>>>(
        S.Xh, S.Xl, S.Wth, S.Wtl, Kb, nullptr, S.Kf, nullptr, nullptr, NROWS, DIM, DIM);

    convert_trans<<<gW, b256>>>(Qw, S.Wth, S.Wtl, DIM, DIM);
    gemm_fp16x3<false, true, false><<<gProj, b256, SMEM_TOTAL>>>(
        S.Xh, S.Xl, S.Wth, S.Wtl, Qb, nullptr, S.Qf, nullptr, nullptr, NROWS, DIM, DIM);

    convert_trans<<<gW, b256>>>(Vw, S.Wth, S.Wtl, DIM, DIM);
    gemm_fp16x3<true, true, false><<<gProj, b256, SMEM_TOTAL>>>(
        S.Xh, S.Xl, S.Wth, S.Wtl, Vb, nullptr, nullptr, S.Vh, S.Vl, NROWS, DIM, DIM);

    // transpose-convert K, Q: [8192][2048] -> planes [2048][8192]
    convert_trans<<<gT, b256>>>(S.Kf, S.Kth, S.Ktl, NROWS, DIM);
    convert_trans<<<gT, b256>>>(S.Qf, S.Qth, S.Qtl, NROWS, DIM);

    // att = Q^T K : M=N=2048, K=8192
    gemm_fp16x3<false, false, false><<<gAtt, b256, SMEM_TOTAL>>>(
        S.Qth, S.Qtl, S.Kth, S.Ktl, nullptr, nullptr, S.ATT, nullptr, nullptr, DIM, DIM, NROWS);

    softmax_kernel<<<DIM, b256>>>(S.ATT, outW, S.wh, S.wl, DIM);

    // out = V @ w^T
    gemm_fp16x3<true, false, false><<<gProj, b256, SMEM_TOTAL>>>(
        S.Vh, S.Vl, S.wh, S.wl, nullptr, nullptr, nullptr, S.Oh, S.Ol, NROWS, DIM, DIM);

    // y = out @ Ow + Ob + X
    convert_trans<<<gW, b256>>>(Ow, S.Wth, S.Wtl, DIM, DIM);
    gemm_fp16x3<false, true, true><<<gProj, b256, SMEM_TOTAL>>>(
        S.Oh, S.Ol, S.Wth, S.Wtl, Ob, X, outY, nullptr, nullptr, NROWS, DIM, DIM);
}

extern "C" void kernel_launch(void* const* d_in, const int* in_sizes, int n_in,
                              void* d_out, int out_size) {
    cudaFuncSetAttribute(gemm_fp16x3<false, true, false>, cudaFuncAttributeMaxDynamicSharedMemorySize, SMEM_TOTAL);
    cudaFuncSetAttribute(gemm_fp16x3<true, true, false>, cudaFuncAttributeMaxDynamicSharedMemorySize, SMEM_TOTAL);
    cudaFuncSetAttribute(gemm_fp16x3<false, false, false>, cudaFuncAttributeMaxDynamicSharedMemorySize, SMEM_TOTAL);
    cudaFuncSetAttribute(gemm_fp16x3<true, false, false>, cudaFuncAttributeMaxDynamicSharedMemorySize, SMEM_TOTAL);
    cudaFuncSetAttribute(gemm_fp16x3<false, true, true>, cudaFuncAttributeMaxDynamicSharedMemorySize, SMEM_TOTAL);

    const float* x = (const float*)d_in[0];
    const float* y = (const float*)d_in[1];

    Scratch S;
    cudaGetSymbolAddress((void**)&S.Xh, g_Xh);   cudaGetSymbolAddress((void**)&S.Xl, g_Xl);
    cudaGetSymbolAddress((void**)&S.Wth, g_Wth); cudaGetSymbolAddress((void**)&S.Wtl, g_Wtl);
    cudaGetSymbolAddress((void**)&S.Kf, g_Kf);   cudaGetSymbolAddress((void**)&S.Qf, g_Qf);
    cudaGetSymbolAddress((void**)&S.Kth, g_Kth); cudaGetSymbolAddress((void**)&S.Ktl, g_Ktl);
    cudaGetSymbolAddress((void**)&S.Qth, g_Qth); cudaGetSymbolAddress((void**)&S.Qtl, g_Qtl);
    cudaGetSymbolAddress((void**)&S.Vh, g_Vh);   cudaGetSymbolAddress((void**)&S.Vl, g_Vl);
    cudaGetSymbolAddress((void**)&S.ATT, g_ATT);
    cudaGetSymbolAddress((void**)&S.wh, g_wh);   cudaGetSymbolAddress((void**)&S.wl, g_wl);
    cudaGetSymbolAddress((void**)&S.Oh, g_Oh);   cudaGetSymbolAddress((void**)&S.Ol, g_Ol);

    float* out = (float*)d_out;
    float* outQy = out;
    float* outQatt = outQy + (size_t)NROWS * DIM;
    float* outFy = outQatt + (size_t)DIM * DIM;
    float* outFatt = outFy + (size_t)NROWS * DIM;

    run_branch(S, x, (const float*)d_in[2], (const float*)d_in[3], (const float*)d_in[4],
               (const float*)d_in[5], (const float*)d_in[6], (const float*)d_in[7],
               (const float*)d_in[8], (const float*)d_in[9], outQy, outQatt);
    run_branch(S, y, (const float*)d_in[10], (const float*)d_in[11], (const float*)d_in[12],
               (const float*)d_in[13], (const float*)d_in[14], (const float*)d_in[15],
               (const float*)d_in[16], (const float*)d_in[17], outFy, outFatt);
}